// round 15
// baseline (speedup 1.0000x reference)
#include <cuda_runtime.h>
#include <cuda_bf16.h>
#include <cstdint>

#define MAXN 100000
#define MAXE 1600000
#define HDIM 128
#define FIN  9
#define GMAX 256
#define SCAN_B 256
#define MAXBLK 512
#define KC   64                 // k per staging phase (bf16 pairs: 32 uints)
#define PC   (KC / 2)           // k-pairs per phase
#define AST  36                 // pair-stride ≡ 4 (mod 32) -> conflict-free frags
#define GEMM_SMEM (4 * 128 * AST * 4)   // 73728 B -> 2 CTA/SM

// -------- scratch (device symbols only; NEVER pass from host — GB300 ATS trap) ----
__device__ __align__(128) float g_dinv[MAXN];
__device__ __align__(128) __nv_bfloat16 g_bufA16[MAXN * HDIM];  // pre-agg (bf16)
__device__ __align__(128) float g_bufB[MAXN * HDIM];            // layer-1 output (fp32)
__device__ __align__(128) float g_s[MAXN];       // per-node scalar relu(h2)·w~
__device__ __align__(128) float g_wtld[HDIM];    // w~ = W3 @ lin_w
__device__ int   g_degc[MAXN];
__device__ int   g_rowstart[MAXN + 1];
__device__ int   g_cursor[MAXN];
__device__ int   g_bsum[MAXBLK];
__device__ __align__(128) int2 g_cedge[MAXE];   // (src, norm-as-int)
__device__ int   g_lo[GMAX];
__device__ int   g_hi[GMAX];

// fp32 -> bf16 hi + bf16 lo (Dekker residual)
__device__ __forceinline__ void bf16split(float f, __nv_bfloat16& hi, __nv_bfloat16& lo) {
    hi = __float2bfloat16(f);
    lo = __float2bfloat16(f - __bfloat162float(hi));
}
__device__ __forceinline__ unsigned packbf(__nv_bfloat16 a, __nv_bfloat16 b) {
    __nv_bfloat162 p = __halves2bfloat162(a, b);   // low = a (k even), high = b (k odd)
    return *reinterpret_cast<unsigned*>(&p);
}

// ====== setup: clear + (last block) w~ gemv + out head init ======
__global__ void k_clear(int n, int g, int nb,
                        const float* __restrict__ W3, const float* __restrict__ b3,
                        const float* __restrict__ lin_w, const float* __restrict__ lb,
                        float* __restrict__ out) {
    if ((int)blockIdx.x == nb) {
        // gemv block: w~ = W3 @ lin_w ; out[k] = b3·lin_w + lin_b
        int k = threadIdx.x;
        __shared__ float sb[HDIM];
        if (k < HDIM) {
            float s = 0.f;
#pragma unroll 8
            for (int c = 0; c < HDIM; c++) s += W3[k * HDIM + c] * lin_w[c];
            g_wtld[k] = s;
            sb[k] = b3[k] * lin_w[k];
        }
        __syncthreads();
        for (int off = HDIM / 2; off > 0; off >>= 1) {
            if (k < off) sb[k] += sb[k + off];
            __syncthreads();
        }
        if (k < g) out[k] = sb[0] + lb[0];
        return;
    }
    int i = blockIdx.x * blockDim.x + threadIdx.x;
    if (i < n) g_degc[i] = 0;
    if (i < g) { g_lo[i] = 0; g_hi[i] = 0; }
}

__global__ void k_deg(const int* __restrict__ dst, int E) {
    int e = blockIdx.x * blockDim.x + threadIdx.x;
    if (e < E) atomicAdd(&g_degc[dst[e]], 1);
}

__global__ void k_scan1(int n) {
    __shared__ int sh[SCAN_B];
    int i = blockIdx.x * SCAN_B + threadIdx.x;
    int v = (i < n) ? g_degc[i] : 0;
    if (i < n) g_dinv[i] = rsqrtf((float)(v + 1));
    sh[threadIdx.x] = v;
    __syncthreads();
    for (int off = 1; off < SCAN_B; off <<= 1) {
        int t = (threadIdx.x >= (unsigned)off) ? sh[threadIdx.x - off] : 0;
        __syncthreads();
        sh[threadIdx.x] += t;
        __syncthreads();
    }
    if (i < n) g_rowstart[i] = sh[threadIdx.x] - v;
    if (threadIdx.x == SCAN_B - 1) g_bsum[blockIdx.x] = sh[SCAN_B - 1];
}

// finalize rowstart + cursors + graph bounds; block-offset reduced in-block
__global__ void k_scan3(const int* __restrict__ batch, int n, int E) {
    __shared__ int red[SCAN_B];
    int b = blockIdx.x;
    int partial = 0;
    for (int j = threadIdx.x; j < b; j += SCAN_B) partial += g_bsum[j];
    red[threadIdx.x] = partial;
    __syncthreads();
    for (int off = SCAN_B / 2; off > 0; off >>= 1) {
        if (threadIdx.x < (unsigned)off) red[threadIdx.x] += red[threadIdx.x + off];
        __syncthreads();
    }
    int boff = red[0];

    int i = b * SCAN_B + threadIdx.x;
    if (i < n) {
        int r = g_rowstart[i] + boff;
        g_rowstart[i] = r;
        g_cursor[i] = r;
        int bb = batch[i];
        if (i == 0) g_lo[bb] = 0;
        else {
            int pb = batch[i - 1];
            if (pb != bb) { g_lo[bb] = i; g_hi[pb] = i; }
        }
        if (i == n - 1) g_hi[bb] = n;
    } else if (i == n) {
        g_rowstart[n] = E;
    }
}

__global__ void k_fill(const int* __restrict__ src, const int* __restrict__ dst, int E) {
    int e = blockIdx.x * blockDim.x + threadIdx.x;
    if (e >= E) return;
    int s = src[e], d = dst[e];
    int pos = atomicAdd(&g_cursor[d], 1);
    float nrm = g_dinv[s] * g_dinv[d];
    g_cedge[pos] = make_int2(s, __float_as_int(nrm));
}

// ======= layer 1 fused: bufB = (Â X) W1 + b1  (gather + shfl + GEMV) =======
__global__ void __launch_bounds__(256) k_layer1(const float* __restrict__ x,
                                                const float* __restrict__ W,
                                                const float* __restrict__ bias, int n) {
    __shared__ float sW1[FIN * HDIM];   // 4.6 KB
    __shared__ float sB[HDIM];
    for (int i = threadIdx.x; i < FIN * HDIM; i += 256) sW1[i] = W[i];
    if (threadIdx.x < HDIM) sB[threadIdx.x] = bias[threadIdx.x];
    __syncthreads();

    int w = (blockIdx.x * blockDim.x + threadIdx.x) >> 5;
    if (w >= n) return;
    int lane = threadIdx.x & 31;
    int rs = g_rowstart[w], re = g_rowstart[w + 1];
    float di = g_dinv[w];
    bool act = lane < FIN;
    float acc = 0.f;
    if (act) acc = x[w * FIN + lane] * di * di;
    int j = rs;
    for (; j + 7 < re; j += 8) {   // 8-deep MLP
        int2 e0 = g_cedge[j],     e1 = g_cedge[j + 1];
        int2 e2 = g_cedge[j + 2], e3 = g_cedge[j + 3];
        int2 e4 = g_cedge[j + 4], e5 = g_cedge[j + 5];
        int2 e6 = g_cedge[j + 6], e7 = g_cedge[j + 7];
        float v0 = 0.f, v1 = 0.f, v2 = 0.f, v3 = 0.f;
        float v4 = 0.f, v5 = 0.f, v6 = 0.f, v7 = 0.f;
        if (act) {
            v0 = x[e0.x * FIN + lane]; v1 = x[e1.x * FIN + lane];
            v2 = x[e2.x * FIN + lane]; v3 = x[e3.x * FIN + lane];
            v4 = x[e4.x * FIN + lane]; v5 = x[e5.x * FIN + lane];
            v6 = x[e6.x * FIN + lane]; v7 = x[e7.x * FIN + lane];
        }
        acc += v0 * __int_as_float(e0.y) + v1 * __int_as_float(e1.y)
             + v2 * __int_as_float(e2.y) + v3 * __int_as_float(e3.y)
             + v4 * __int_as_float(e4.y) + v5 * __int_as_float(e5.y)
             + v6 * __int_as_float(e6.y) + v7 * __int_as_float(e7.y);
    }
    for (; j < re; j++) {
        int2 e = g_cedge[j];
        if (act) acc += x[e.x * FIN + lane] * __int_as_float(e.y);
    }
    // broadcast 9 aggregated features to all lanes
    float xv[FIN];
#pragma unroll
    for (int f = 0; f < FIN; f++) xv[f] = __shfl_sync(0xffffffffu, acc, f);
    // each lane computes 4 output columns
    int c = lane * 4;
    float4 o = make_float4(sB[c], sB[c + 1], sB[c + 2], sB[c + 3]);
#pragma unroll
    for (int f = 0; f < FIN; f++) {
        float4 wv = *reinterpret_cast<const float4*>(&sW1[f * HDIM + c]);
        o.x += xv[f] * wv.x; o.y += xv[f] * wv.y;
        o.z += xv[f] * wv.z; o.w += xv[f] * wv.w;
    }
    *reinterpret_cast<float4*>(&g_bufB[w * HDIM + c]) = o;
}

// ====== hidden GEMM: 3-term bf16 split warp-MMA (m16n8k16), KC=64, 2 phases ======
__global__ void __launch_bounds__(256) k_gemm_mma(const float* __restrict__ W, int n) {
    extern __shared__ unsigned smu[];
    unsigned* sAhi = smu;                   // [128 rows][AST pairs]
    unsigned* sAlo = smu + 128 * AST;
    unsigned* sWhi = smu + 2 * 128 * AST;   // [128 nn][AST pairs]
    unsigned* sWlo = smu + 3 * 128 * AST;
    int tid = threadIdx.x;
    int node0 = blockIdx.x * 128;

    int wid = tid >> 5, lane = tid & 31;
    int m0 = wid * 16;
    int lr = lane >> 2;      // 0..7
    int lc = lane & 3;       // 0..3

    float d[16][4];
#pragma unroll
    for (int t = 0; t < 16; t++)
#pragma unroll
        for (int j = 0; j < 4; j++) d[t][j] = 0.f;

#pragma unroll 1
    for (int p = 0; p < 2; p++) {
        int k0 = p * KC;
        if (p) __syncthreads();
        // stage A: 128 rows x 32 k-pairs (relu + split + pack)
        for (int idx = tid; idx < 128 * PC; idx += 256) {
            int r = idx >> 5, pc = idx & (PC - 1);
            int k = k0 + pc * 2;
            float v0 = 0.f, v1 = 0.f;
            if (node0 + r < n) {
                const float* row = &g_bufB[(node0 + r) * HDIM + k];
                v0 = fmaxf(row[0], 0.f);
                v1 = fmaxf(row[1], 0.f);
            }
            __nv_bfloat16 h0, l0, h1, l1;
            bf16split(v0, h0, l0);
            bf16split(v1, h1, l1);
            sAhi[r * AST + pc] = packbf(h0, h1);
            sAlo[r * AST + pc] = packbf(l0, l1);
        }
        // stage W^T: sW[nn][pc] pairs = (W[k][nn], W[k+1][nn])
        for (int idx = tid; idx < PC * 128; idx += 256) {
            int pc = idx >> 7, nn = idx & 127;
            int k = k0 + pc * 2;
            float v0 = __ldg(&W[k * HDIM + nn]);
            float v1 = __ldg(&W[(k + 1) * HDIM + nn]);
            __nv_bfloat16 h0, l0, h1, l1;
            bf16split(v0, h0, l0);
            bf16split(v1, h1, l1);
            sWhi[nn * AST + pc] = packbf(h0, h1);
            sWlo[nn * AST + pc] = packbf(l0, l1);
        }
        __syncthreads();

        const unsigned* pah = &sAhi[(m0 + lr) * AST + lc];
        const unsigned* pal = &sAlo[(m0 + lr) * AST + lc];

#pragma unroll
        for (int kc = 0; kc < PC / 8; kc++) {   // 4 chunks of k16 (8 pairs)
            int kb = kc * 8;
            unsigned ah0 = pah[kb],     ah1 = pah[8 * AST + kb];
            unsigned ah2 = pah[kb + 4], ah3 = pah[8 * AST + kb + 4];
            unsigned al0 = pal[kb],     al1 = pal[8 * AST + kb];
            unsigned al2 = pal[kb + 4], al3 = pal[8 * AST + kb + 4];
#pragma unroll
            for (int t = 0; t < 16; t++) {
                const unsigned* pbh = &sWhi[(t * 8 + lr) * AST + kb + lc];
                const unsigned* pbl = &sWlo[(t * 8 + lr) * AST + kb + lc];
                unsigned bh0 = pbh[0], bh1 = pbh[4];
                unsigned bl0 = pbl[0], bl1 = pbl[4];
                asm volatile(
                    "mma.sync.aligned.m16n8k16.row.col.f32.bf16.bf16.f32 "
                    "{%0,%1,%2,%3}, {%4,%5,%6,%7}, {%8,%9}, {%0,%1,%2,%3};"
                    : "+f"(d[t][0]), "+f"(d[t][1]), "+f"(d[t][2]), "+f"(d[t][3])
                    : "r"(ah0), "r"(ah1), "r"(ah2), "r"(ah3), "r"(bh0), "r"(bh1));
                asm volatile(
                    "mma.sync.aligned.m16n8k16.row.col.f32.bf16.bf16.f32 "
                    "{%0,%1,%2,%3}, {%4,%5,%6,%7}, {%8,%9}, {%0,%1,%2,%3};"
                    : "+f"(d[t][0]), "+f"(d[t][1]), "+f"(d[t][2]), "+f"(d[t][3])
                    : "r"(ah0), "r"(ah1), "r"(ah2), "r"(ah3), "r"(bl0), "r"(bl1));
                asm volatile(
                    "mma.sync.aligned.m16n8k16.row.col.f32.bf16.bf16.f32 "
                    "{%0,%1,%2,%3}, {%4,%5,%6,%7}, {%8,%9}, {%0,%1,%2,%3};"
                    : "+f"(d[t][0]), "+f"(d[t][1]), "+f"(d[t][2]), "+f"(d[t][3])
                    : "r"(al0), "r"(al1), "r"(al2), "r"(al3), "r"(bh0), "r"(bh1));
            }
        }
    }

    int row0 = node0 + m0 + lr;
    int row1 = row0 + 8;
#pragma unroll
    for (int t = 0; t < 16; t++) {
        int col = t * 8 + lc * 2;
        if (row0 < n) {
            __nv_bfloat162 pp = __floats2bfloat162_rn(d[t][0], d[t][1]);
            *reinterpret_cast<unsigned*>(&g_bufA16[row0 * HDIM + col]) =
                *reinterpret_cast<unsigned*>(&pp);
        }
        if (row1 < n) {
            __nv_bfloat162 pp = __floats2bfloat162_rn(d[t][2], d[t][3]);
            *reinterpret_cast<unsigned*>(&g_bufA16[row1 * HDIM + col]) =
                *reinterpret_cast<unsigned*>(&pp);
        }
    }
}

// ======= layer-2 aggregate + relu + dot(w~): 2 warps/node, smem combine ======
__device__ __forceinline__ float4 ld_row4(int node, int q) {
    uint2 raw = *reinterpret_cast<const uint2*>(&g_bufA16[node * HDIM + q]);
    __nv_bfloat162 p0 = *reinterpret_cast<__nv_bfloat162*>(&raw.x);
    __nv_bfloat162 p1 = *reinterpret_cast<__nv_bfloat162*>(&raw.y);
    float2 f0 = __bfloat1622float2(p0);
    float2 f1 = __bfloat1622float2(p1);
    return make_float4(f0.x, f0.y, f1.x, f1.y);
}

__global__ void __launch_bounds__(256) k_gather_dot(const float* __restrict__ bias, int n) {
    __shared__ float4 sacc[8][32];
    int wid = threadIdx.x >> 5;          // 0..7
    int lane = threadIdx.x & 31;
    int node = blockIdx.x * 4 + (wid >> 1);
    int half = wid & 1;
    int q = lane * 4;
    float4 acc = make_float4(0.f, 0.f, 0.f, 0.f);

    if (node < n) {
        int rs = g_rowstart[node], re = g_rowstart[node + 1];
        if (half == 0) {   // self loop
            float di = g_dinv[node];
            float d2 = di * di;
            float4 self = ld_row4(node, q);
            acc = make_float4(self.x * d2, self.y * d2, self.z * d2, self.w * d2);
        }
        // alternate 8-edge chunks: half h takes [rs+h*8, +8), [rs+16+h*8, +8), ...
        for (int base = rs + half * 8; base < re; base += 16) {
            if (base + 8 <= re) {
                int2 e0 = g_cedge[base],     e1 = g_cedge[base + 1];
                int2 e2 = g_cedge[base + 2], e3 = g_cedge[base + 3];
                int2 e4 = g_cedge[base + 4], e5 = g_cedge[base + 5];
                int2 e6 = g_cedge[base + 6], e7 = g_cedge[base + 7];
                float4 v0 = ld_row4(e0.x, q), v1 = ld_row4(e1.x, q);
                float4 v2 = ld_row4(e2.x, q), v3 = ld_row4(e3.x, q);
                float4 v4 = ld_row4(e4.x, q), v5 = ld_row4(e5.x, q);
                float4 v6 = ld_row4(e6.x, q), v7 = ld_row4(e7.x, q);
                float w0 = __int_as_float(e0.y), w1 = __int_as_float(e1.y);
                float w2 = __int_as_float(e2.y), w3 = __int_as_float(e3.y);
                float w4 = __int_as_float(e4.y), w5 = __int_as_float(e5.y);
                float w6 = __int_as_float(e6.y), w7 = __int_as_float(e7.y);
                acc.x += v0.x*w0 + v1.x*w1 + v2.x*w2 + v3.x*w3 + v4.x*w4 + v5.x*w5 + v6.x*w6 + v7.x*w7;
                acc.y += v0.y*w0 + v1.y*w1 + v2.y*w2 + v3.y*w3 + v4.y*w4 + v5.y*w5 + v6.y*w6 + v7.y*w7;
                acc.z += v0.z*w0 + v1.z*w1 + v2.z*w2 + v3.z*w3 + v4.z*w4 + v5.z*w5 + v6.z*w6 + v7.z*w7;
                acc.w += v0.w*w0 + v1.w*w1 + v2.w*w2 + v3.w*w3 + v4.w*w4 + v5.w*w5 + v6.w*w6 + v7.w*w7;
            } else {
                for (int j = base; j < re; j++) {
                    int2 e = g_cedge[j];
                    float wt = __int_as_float(e.y);
                    float4 v = ld_row4(e.x, q);
                    acc.x += v.x * wt; acc.y += v.y * wt;
                    acc.z += v.z * wt; acc.w += v.w * wt;
                }
            }
        }
    }
    sacc[wid][lane] = acc;
    __syncthreads();
    if (half == 0 && node < n) {
        float4 o = sacc[wid + 1][lane];
        acc.x += o.x; acc.y += o.y; acc.z += o.z; acc.w += o.w;
        float4 b = __ldg(reinterpret_cast<const float4*>(&bias[q]));
        acc.x += b.x; acc.y += b.y; acc.z += b.z; acc.w += b.w;
        float4 wt = __ldg(reinterpret_cast<const float4*>(&g_wtld[q]));
        float v = fmaxf(acc.x, 0.f) * wt.x + fmaxf(acc.y, 0.f) * wt.y
                + fmaxf(acc.z, 0.f) * wt.z + fmaxf(acc.w, 0.f) * wt.w;
#pragma unroll
        for (int off = 16; off > 0; off >>= 1)
            v += __shfl_down_sync(0xffffffffu, v, off);
        if (lane == 0) g_s[node] = v;
    }
}

// scalar aggregate + pool
__global__ void k_spool(const int* __restrict__ batch, float* __restrict__ out, int n) {
    int d = blockIdx.x * blockDim.x + threadIdx.x;
    if (d >= n) return;
    int rs = g_rowstart[d], re = g_rowstart[d + 1];
    float di = g_dinv[d];
    float acc = di * di * g_s[d];
    int j = rs;
    for (; j + 3 < re; j += 4) {
        int2 e0 = g_cedge[j],     e1 = g_cedge[j + 1];
        int2 e2 = g_cedge[j + 2], e3 = g_cedge[j + 3];
        float s0 = g_s[e0.x], s1 = g_s[e1.x], s2 = g_s[e2.x], s3 = g_s[e3.x];
        acc += s0 * __int_as_float(e0.y) + s1 * __int_as_float(e1.y)
             + s2 * __int_as_float(e2.y) + s3 * __int_as_float(e3.y);
    }
    for (; j < re; j++) {
        int2 e = g_cedge[j];
        acc += g_s[e.x] * __int_as_float(e.y);
    }
    int b = batch[d];
    float inv = 1.f / (float)(g_hi[b] - g_lo[b]);
    asm volatile("red.global.add.f32 [%0], %1;" :: "l"(&out[b]), "f"(acc * inv) : "memory");
}

extern "C" void kernel_launch(void* const* d_in, const int* in_sizes, int n_in,
                              void* d_out, int out_size) {
    const float* x     = (const float*)d_in[0];
    const int*   ei    = (const int*)d_in[1];
    const int*   batch = (const int*)d_in[2];
    const float* W1 = (const float*)d_in[3];
    const float* b1 = (const float*)d_in[4];
    const float* W2 = (const float*)d_in[5];
    const float* b2 = (const float*)d_in[6];
    const float* W3 = (const float*)d_in[7];
    const float* b3 = (const float*)d_in[8];
    const float* lw = (const float*)d_in[9];
    const float* lb = (const float*)d_in[10];
    float* out = (float*)d_out;

    int N = in_sizes[0] / FIN;
    int E = in_sizes[1] / 2;
    int G = out_size;

    const int* src = ei;
    const int* dst = ei + E;

    int nb  = (N + SCAN_B - 1) / SCAN_B;
    int eb  = (E + 255) / 256;
    int wb  = (N * 32 + 255) / 256;
    int mb  = (N + 127) / 128;
    int gdb = (N + 3) / 4;                  // gather_dot: 4 nodes/CTA

    cudaFuncSetAttribute(k_gemm_mma, cudaFuncAttributeMaxDynamicSharedMemorySize, GEMM_SMEM);

    // ---- CSR build + bounds (+ fused gemv/out-head in clear) ----
    k_clear<<<nb + 1, SCAN_B>>>(N, G, nb, W3, b3, lw, lb, out);
    k_deg<<<eb, 256>>>(dst, E);
    k_scan1<<<nb, SCAN_B>>>(N);
    k_scan3<<<(N + 256) / 256, 256>>>(batch, N, E);
    k_fill<<<eb, 256>>>(src, dst, E);

    // ---- layer 1 (fused gather + GEMV) ----
    k_layer1<<<wb, 256>>>(x, W1, b1, N);
    // ---- layer 2 GEMM (bf16 split MMA) ----
    k_gemm_mma<<<mb, 256, GEMM_SMEM>>>(W2, N);
    // ---- layer-2 gather + relu + dot (2 warps/node) ----
    k_gather_dot<<<gdb, 256>>>(b2, N);
    // ---- layer-3 scalar aggregate + pool ----
    k_spool<<<(N + 255) / 256, 256>>>(batch, out, N);
}

// round 16
// speedup vs baseline: 1.1620x; 1.1620x over previous
#include <cuda_runtime.h>
#include <cuda_bf16.h>
#include <cstdint>

#define MAXN 100000
#define MAXE 1600000
#define HDIM 128
#define FIN  9
#define GMAX 256
#define SCAN_B 256
#define MAXBLK 512
#define KC   64                 // k per staging phase (bf16 pairs: 32 uints)
#define PC   (KC / 2)           // k-pairs per phase
#define AST  36                 // pair-stride ≡ 4 (mod 32) -> conflict-free frags
#define GEMM_SMEM (4 * 128 * AST * 4)   // 73728 B -> 2 CTA/SM

// -------- scratch (device symbols only; NEVER pass from host — GB300 ATS trap) ----
__device__ __align__(128) float g_dinv[MAXN];
__device__ __align__(128) __nv_bfloat16 g_bufA16[MAXN * HDIM];  // pre-agg (bf16)
__device__ __align__(128) float g_bufB[MAXN * HDIM];            // layer-1 output (fp32)
__device__ __align__(128) float g_s[MAXN];       // per-node scalar relu(h2)·w~
__device__ __align__(128) float g_wtld[HDIM];    // w~ = W3 @ lin_w
__device__ int   g_degc[MAXN];
__device__ int   g_rowstart[MAXN + 1];
__device__ int   g_cursor[MAXN];
__device__ int   g_bsum[MAXBLK];
__device__ __align__(128) int2 g_cedge[MAXE];   // (src, norm-as-int)
__device__ int   g_lo[GMAX];
__device__ int   g_hi[GMAX];

// fp32 -> bf16 hi + bf16 lo (Dekker residual)
__device__ __forceinline__ void bf16split(float f, __nv_bfloat16& hi, __nv_bfloat16& lo) {
    hi = __float2bfloat16(f);
    lo = __float2bfloat16(f - __bfloat162float(hi));
}
__device__ __forceinline__ unsigned packbf(__nv_bfloat16 a, __nv_bfloat16 b) {
    __nv_bfloat162 p = __halves2bfloat162(a, b);   // low = a (k even), high = b (k odd)
    return *reinterpret_cast<unsigned*>(&p);
}

// ====== setup: clear + (last block) w~ gemv + out head init ======
__global__ void k_clear(int n, int g, int nb,
                        const float* __restrict__ W3, const float* __restrict__ b3,
                        const float* __restrict__ lin_w, const float* __restrict__ lb,
                        float* __restrict__ out) {
    if ((int)blockIdx.x == nb) {
        // gemv block: w~ = W3 @ lin_w ; out[k] = b3·lin_w + lin_b
        int k = threadIdx.x;
        __shared__ float sb[HDIM];
        if (k < HDIM) {
            float s = 0.f;
#pragma unroll 8
            for (int c = 0; c < HDIM; c++) s += W3[k * HDIM + c] * lin_w[c];
            g_wtld[k] = s;
            sb[k] = b3[k] * lin_w[k];
        }
        __syncthreads();
        for (int off = HDIM / 2; off > 0; off >>= 1) {
            if (k < off) sb[k] += sb[k + off];
            __syncthreads();
        }
        if (k < g) out[k] = sb[0] + lb[0];
        return;
    }
    int i = blockIdx.x * blockDim.x + threadIdx.x;
    if (i < n) g_degc[i] = 0;
    if (i < g) { g_lo[i] = 0; g_hi[i] = 0; }
}

__global__ void k_deg(const int* __restrict__ dst, int E) {
    int e = blockIdx.x * blockDim.x + threadIdx.x;
    if (e < E) atomicAdd(&g_degc[dst[e]], 1);
}

__global__ void k_scan1(int n) {
    __shared__ int sh[SCAN_B];
    int i = blockIdx.x * SCAN_B + threadIdx.x;
    int v = (i < n) ? g_degc[i] : 0;
    if (i < n) g_dinv[i] = rsqrtf((float)(v + 1));
    sh[threadIdx.x] = v;
    __syncthreads();
    for (int off = 1; off < SCAN_B; off <<= 1) {
        int t = (threadIdx.x >= (unsigned)off) ? sh[threadIdx.x - off] : 0;
        __syncthreads();
        sh[threadIdx.x] += t;
        __syncthreads();
    }
    if (i < n) g_rowstart[i] = sh[threadIdx.x] - v;
    if (threadIdx.x == SCAN_B - 1) g_bsum[blockIdx.x] = sh[SCAN_B - 1];
}

// finalize rowstart + cursors + graph bounds; block-offset reduced in-block
__global__ void k_scan3(const int* __restrict__ batch, int n, int E) {
    __shared__ int red[SCAN_B];
    int b = blockIdx.x;
    int partial = 0;
    for (int j = threadIdx.x; j < b; j += SCAN_B) partial += g_bsum[j];
    red[threadIdx.x] = partial;
    __syncthreads();
    for (int off = SCAN_B / 2; off > 0; off >>= 1) {
        if (threadIdx.x < (unsigned)off) red[threadIdx.x] += red[threadIdx.x + off];
        __syncthreads();
    }
    int boff = red[0];

    int i = b * SCAN_B + threadIdx.x;
    if (i < n) {
        int r = g_rowstart[i] + boff;
        g_rowstart[i] = r;
        g_cursor[i] = r;
        int bb = batch[i];
        if (i == 0) g_lo[bb] = 0;
        else {
            int pb = batch[i - 1];
            if (pb != bb) { g_lo[bb] = i; g_hi[pb] = i; }
        }
        if (i == n - 1) g_hi[bb] = n;
    } else if (i == n) {
        g_rowstart[n] = E;
    }
}

__global__ void k_fill(const int* __restrict__ src, const int* __restrict__ dst, int E) {
    int e = blockIdx.x * blockDim.x + threadIdx.x;
    if (e >= E) return;
    int s = src[e], d = dst[e];
    int pos = atomicAdd(&g_cursor[d], 1);
    float nrm = g_dinv[s] * g_dinv[d];
    g_cedge[pos] = make_int2(s, __float_as_int(nrm));
}

// ======= layer 1 fused: bufB = (Â X) W1 + b1  (gather + shfl + GEMV) =======
__global__ void __launch_bounds__(256) k_layer1(const float* __restrict__ x,
                                                const float* __restrict__ W,
                                                const float* __restrict__ bias, int n) {
    __shared__ float sW1[FIN * HDIM];   // 4.6 KB
    __shared__ float sB[HDIM];
    for (int i = threadIdx.x; i < FIN * HDIM; i += 256) sW1[i] = W[i];
    if (threadIdx.x < HDIM) sB[threadIdx.x] = bias[threadIdx.x];
    __syncthreads();

    int w = (blockIdx.x * blockDim.x + threadIdx.x) >> 5;
    if (w >= n) return;
    int lane = threadIdx.x & 31;
    int rs = g_rowstart[w], re = g_rowstart[w + 1];
    float di = g_dinv[w];
    bool act = lane < FIN;
    float acc = 0.f;
    if (act) acc = x[w * FIN + lane] * di * di;
    int j = rs;
    for (; j + 7 < re; j += 8) {   // 8-deep MLP
        int2 e0 = g_cedge[j],     e1 = g_cedge[j + 1];
        int2 e2 = g_cedge[j + 2], e3 = g_cedge[j + 3];
        int2 e4 = g_cedge[j + 4], e5 = g_cedge[j + 5];
        int2 e6 = g_cedge[j + 6], e7 = g_cedge[j + 7];
        float v0 = 0.f, v1 = 0.f, v2 = 0.f, v3 = 0.f;
        float v4 = 0.f, v5 = 0.f, v6 = 0.f, v7 = 0.f;
        if (act) {
            v0 = x[e0.x * FIN + lane]; v1 = x[e1.x * FIN + lane];
            v2 = x[e2.x * FIN + lane]; v3 = x[e3.x * FIN + lane];
            v4 = x[e4.x * FIN + lane]; v5 = x[e5.x * FIN + lane];
            v6 = x[e6.x * FIN + lane]; v7 = x[e7.x * FIN + lane];
        }
        acc += v0 * __int_as_float(e0.y) + v1 * __int_as_float(e1.y)
             + v2 * __int_as_float(e2.y) + v3 * __int_as_float(e3.y)
             + v4 * __int_as_float(e4.y) + v5 * __int_as_float(e5.y)
             + v6 * __int_as_float(e6.y) + v7 * __int_as_float(e7.y);
    }
    for (; j < re; j++) {
        int2 e = g_cedge[j];
        if (act) acc += x[e.x * FIN + lane] * __int_as_float(e.y);
    }
    // broadcast 9 aggregated features to all lanes
    float xv[FIN];
#pragma unroll
    for (int f = 0; f < FIN; f++) xv[f] = __shfl_sync(0xffffffffu, acc, f);
    // each lane computes 4 output columns
    int c = lane * 4;
    float4 o = make_float4(sB[c], sB[c + 1], sB[c + 2], sB[c + 3]);
#pragma unroll
    for (int f = 0; f < FIN; f++) {
        float4 wv = *reinterpret_cast<const float4*>(&sW1[f * HDIM + c]);
        o.x += xv[f] * wv.x; o.y += xv[f] * wv.y;
        o.z += xv[f] * wv.z; o.w += xv[f] * wv.w;
    }
    *reinterpret_cast<float4*>(&g_bufB[w * HDIM + c]) = o;
}

// ====== hidden GEMM: 3-term bf16 split warp-MMA (m16n8k16), KC=64, 2 phases ======
__global__ void __launch_bounds__(256) k_gemm_mma(const float* __restrict__ W, int n) {
    extern __shared__ unsigned smu[];
    unsigned* sAhi = smu;                   // [128 rows][AST pairs]
    unsigned* sAlo = smu + 128 * AST;
    unsigned* sWhi = smu + 2 * 128 * AST;   // [128 nn][AST pairs]
    unsigned* sWlo = smu + 3 * 128 * AST;
    int tid = threadIdx.x;
    int node0 = blockIdx.x * 128;

    int wid = tid >> 5, lane = tid & 31;
    int m0 = wid * 16;
    int lr = lane >> 2;      // 0..7
    int lc = lane & 3;       // 0..3

    float d[16][4];
#pragma unroll
    for (int t = 0; t < 16; t++)
#pragma unroll
        for (int j = 0; j < 4; j++) d[t][j] = 0.f;

#pragma unroll 1
    for (int p = 0; p < 2; p++) {
        int k0 = p * KC;
        if (p) __syncthreads();
        // stage A: 128 rows x 32 k-pairs (relu + split + pack)
        for (int idx = tid; idx < 128 * PC; idx += 256) {
            int r = idx >> 5, pc = idx & (PC - 1);
            int k = k0 + pc * 2;
            float v0 = 0.f, v1 = 0.f;
            if (node0 + r < n) {
                const float* row = &g_bufB[(node0 + r) * HDIM + k];
                v0 = fmaxf(row[0], 0.f);
                v1 = fmaxf(row[1], 0.f);
            }
            __nv_bfloat16 h0, l0, h1, l1;
            bf16split(v0, h0, l0);
            bf16split(v1, h1, l1);
            sAhi[r * AST + pc] = packbf(h0, h1);
            sAlo[r * AST + pc] = packbf(l0, l1);
        }
        // stage W^T: sW[nn][pc] pairs = (W[k][nn], W[k+1][nn])
        for (int idx = tid; idx < PC * 128; idx += 256) {
            int pc = idx >> 7, nn = idx & 127;
            int k = k0 + pc * 2;
            float v0 = __ldg(&W[k * HDIM + nn]);
            float v1 = __ldg(&W[(k + 1) * HDIM + nn]);
            __nv_bfloat16 h0, l0, h1, l1;
            bf16split(v0, h0, l0);
            bf16split(v1, h1, l1);
            sWhi[nn * AST + pc] = packbf(h0, h1);
            sWlo[nn * AST + pc] = packbf(l0, l1);
        }
        __syncthreads();

        const unsigned* pah = &sAhi[(m0 + lr) * AST + lc];
        const unsigned* pal = &sAlo[(m0 + lr) * AST + lc];

#pragma unroll
        for (int kc = 0; kc < PC / 8; kc++) {   // 4 chunks of k16 (8 pairs)
            int kb = kc * 8;
            unsigned ah0 = pah[kb],     ah1 = pah[8 * AST + kb];
            unsigned ah2 = pah[kb + 4], ah3 = pah[8 * AST + kb + 4];
            unsigned al0 = pal[kb],     al1 = pal[8 * AST + kb];
            unsigned al2 = pal[kb + 4], al3 = pal[8 * AST + kb + 4];
#pragma unroll
            for (int t = 0; t < 16; t++) {
                const unsigned* pbh = &sWhi[(t * 8 + lr) * AST + kb + lc];
                const unsigned* pbl = &sWlo[(t * 8 + lr) * AST + kb + lc];
                unsigned bh0 = pbh[0], bh1 = pbh[4];
                unsigned bl0 = pbl[0], bl1 = pbl[4];
                asm volatile(
                    "mma.sync.aligned.m16n8k16.row.col.f32.bf16.bf16.f32 "
                    "{%0,%1,%2,%3}, {%4,%5,%6,%7}, {%8,%9}, {%0,%1,%2,%3};"
                    : "+f"(d[t][0]), "+f"(d[t][1]), "+f"(d[t][2]), "+f"(d[t][3])
                    : "r"(ah0), "r"(ah1), "r"(ah2), "r"(ah3), "r"(bh0), "r"(bh1));
                asm volatile(
                    "mma.sync.aligned.m16n8k16.row.col.f32.bf16.bf16.f32 "
                    "{%0,%1,%2,%3}, {%4,%5,%6,%7}, {%8,%9}, {%0,%1,%2,%3};"
                    : "+f"(d[t][0]), "+f"(d[t][1]), "+f"(d[t][2]), "+f"(d[t][3])
                    : "r"(ah0), "r"(ah1), "r"(ah2), "r"(ah3), "r"(bl0), "r"(bl1));
                asm volatile(
                    "mma.sync.aligned.m16n8k16.row.col.f32.bf16.bf16.f32 "
                    "{%0,%1,%2,%3}, {%4,%5,%6,%7}, {%8,%9}, {%0,%1,%2,%3};"
                    : "+f"(d[t][0]), "+f"(d[t][1]), "+f"(d[t][2]), "+f"(d[t][3])
                    : "r"(al0), "r"(al1), "r"(al2), "r"(al3), "r"(bh0), "r"(bh1));
            }
        }
    }

    int row0 = node0 + m0 + lr;
    int row1 = row0 + 8;
#pragma unroll
    for (int t = 0; t < 16; t++) {
        int col = t * 8 + lc * 2;
        if (row0 < n) {
            __nv_bfloat162 pp = __floats2bfloat162_rn(d[t][0], d[t][1]);
            *reinterpret_cast<unsigned*>(&g_bufA16[row0 * HDIM + col]) =
                *reinterpret_cast<unsigned*>(&pp);
        }
        if (row1 < n) {
            __nv_bfloat162 pp = __floats2bfloat162_rn(d[t][2], d[t][3]);
            *reinterpret_cast<unsigned*>(&g_bufA16[row1 * HDIM + col]) =
                *reinterpret_cast<unsigned*>(&pp);
        }
    }
}

// ======= layer-2 aggregate + relu + dot(w~): warp per node (R14-proven) ======
__device__ __forceinline__ float4 ld_row4(int node, int q) {
    uint2 raw = *reinterpret_cast<const uint2*>(&g_bufA16[node * HDIM + q]);
    __nv_bfloat162 p0 = *reinterpret_cast<__nv_bfloat162*>(&raw.x);
    __nv_bfloat162 p1 = *reinterpret_cast<__nv_bfloat162*>(&raw.y);
    float2 f0 = __bfloat1622float2(p0);
    float2 f1 = __bfloat1622float2(p1);
    return make_float4(f0.x, f0.y, f1.x, f1.y);
}

__global__ void k_gather_dot(const float* __restrict__ bias, int n) {
    int w = (blockIdx.x * blockDim.x + threadIdx.x) >> 5;
    if (w >= n) return;
    int lane = threadIdx.x & 31;
    int q = lane * 4;
    int rs = g_rowstart[w], re = g_rowstart[w + 1];
    float di = g_dinv[w];
    float4 self = ld_row4(w, q);
    float d2 = di * di;
    float4 acc = make_float4(self.x * d2, self.y * d2, self.z * d2, self.w * d2);

    int j = rs;
    for (; j + 7 < re; j += 8) {   // 8-deep MLP
        int2 e0 = g_cedge[j],     e1 = g_cedge[j + 1];
        int2 e2 = g_cedge[j + 2], e3 = g_cedge[j + 3];
        int2 e4 = g_cedge[j + 4], e5 = g_cedge[j + 5];
        int2 e6 = g_cedge[j + 6], e7 = g_cedge[j + 7];
        float4 v0 = ld_row4(e0.x, q), v1 = ld_row4(e1.x, q);
        float4 v2 = ld_row4(e2.x, q), v3 = ld_row4(e3.x, q);
        float4 v4 = ld_row4(e4.x, q), v5 = ld_row4(e5.x, q);
        float4 v6 = ld_row4(e6.x, q), v7 = ld_row4(e7.x, q);
        float w0 = __int_as_float(e0.y), w1 = __int_as_float(e1.y);
        float w2 = __int_as_float(e2.y), w3 = __int_as_float(e3.y);
        float w4 = __int_as_float(e4.y), w5 = __int_as_float(e5.y);
        float w6 = __int_as_float(e6.y), w7 = __int_as_float(e7.y);
        acc.x += v0.x*w0 + v1.x*w1 + v2.x*w2 + v3.x*w3 + v4.x*w4 + v5.x*w5 + v6.x*w6 + v7.x*w7;
        acc.y += v0.y*w0 + v1.y*w1 + v2.y*w2 + v3.y*w3 + v4.y*w4 + v5.y*w5 + v6.y*w6 + v7.y*w7;
        acc.z += v0.z*w0 + v1.z*w1 + v2.z*w2 + v3.z*w3 + v4.z*w4 + v5.z*w5 + v6.z*w6 + v7.z*w7;
        acc.w += v0.w*w0 + v1.w*w1 + v2.w*w2 + v3.w*w3 + v4.w*w4 + v5.w*w5 + v6.w*w6 + v7.w*w7;
    }
    for (; j < re; j++) {
        int2 e = g_cedge[j];
        float wt = __int_as_float(e.y);
        float4 v = ld_row4(e.x, q);
        acc.x += v.x * wt; acc.y += v.y * wt; acc.z += v.z * wt; acc.w += v.w * wt;
    }
    float4 b = __ldg(reinterpret_cast<const float4*>(&bias[q]));
    acc.x += b.x; acc.y += b.y; acc.z += b.z; acc.w += b.w;
    float4 wt = __ldg(reinterpret_cast<const float4*>(&g_wtld[q]));
    float v = fmaxf(acc.x, 0.f) * wt.x + fmaxf(acc.y, 0.f) * wt.y
            + fmaxf(acc.z, 0.f) * wt.z + fmaxf(acc.w, 0.f) * wt.w;
#pragma unroll
    for (int off = 16; off > 0; off >>= 1)
        v += __shfl_down_sync(0xffffffffu, v, off);
    if (lane == 0) g_s[w] = v;
}

// scalar aggregate + pool
__global__ void k_spool(const int* __restrict__ batch, float* __restrict__ out, int n) {
    int d = blockIdx.x * blockDim.x + threadIdx.x;
    if (d >= n) return;
    int rs = g_rowstart[d], re = g_rowstart[d + 1];
    float di = g_dinv[d];
    float acc = di * di * g_s[d];
    int j = rs;
    for (; j + 3 < re; j += 4) {
        int2 e0 = g_cedge[j],     e1 = g_cedge[j + 1];
        int2 e2 = g_cedge[j + 2], e3 = g_cedge[j + 3];
        float s0 = g_s[e0.x], s1 = g_s[e1.x], s2 = g_s[e2.x], s3 = g_s[e3.x];
        acc += s0 * __int_as_float(e0.y) + s1 * __int_as_float(e1.y)
             + s2 * __int_as_float(e2.y) + s3 * __int_as_float(e3.y);
    }
    for (; j < re; j++) {
        int2 e = g_cedge[j];
        acc += g_s[e.x] * __int_as_float(e.y);
    }
    int b = batch[d];
    float inv = 1.f / (float)(g_hi[b] - g_lo[b]);
    asm volatile("red.global.add.f32 [%0], %1;" :: "l"(&out[b]), "f"(acc * inv) : "memory");
}

extern "C" void kernel_launch(void* const* d_in, const int* in_sizes, int n_in,
                              void* d_out, int out_size) {
    const float* x     = (const float*)d_in[0];
    const int*   ei    = (const int*)d_in[1];
    const int*   batch = (const int*)d_in[2];
    const float* W1 = (const float*)d_in[3];
    const float* b1 = (const float*)d_in[4];
    const float* W2 = (const float*)d_in[5];
    const float* b2 = (const float*)d_in[6];
    const float* W3 = (const float*)d_in[7];
    const float* b3 = (const float*)d_in[8];
    const float* lw = (const float*)d_in[9];
    const float* lb = (const float*)d_in[10];
    float* out = (float*)d_out;

    int N = in_sizes[0] / FIN;
    int E = in_sizes[1] / 2;
    int G = out_size;

    const int* src = ei;
    const int* dst = ei + E;

    int nb  = (N + SCAN_B - 1) / SCAN_B;
    int eb  = (E + 255) / 256;
    int wb  = (N * 32 + 255) / 256;
    int mb  = (N + 127) / 128;

    cudaFuncSetAttribute(k_gemm_mma, cudaFuncAttributeMaxDynamicSharedMemorySize, GEMM_SMEM);

    // ---- CSR build + bounds (+ fused gemv/out-head in clear) ----
    k_clear<<<nb + 1, SCAN_B>>>(N, G, nb, W3, b3, lw, lb, out);
    k_deg<<<eb, 256>>>(dst, E);
    k_scan1<<<nb, SCAN_B>>>(N);
    k_scan3<<<(N + 256) / 256, 256>>>(batch, N, E);
    k_fill<<<eb, 256>>>(src, dst, E);

    // ---- layer 1 (fused gather + GEMV) ----
    k_layer1<<<wb, 256>>>(x, W1, b1, N);
    // ---- layer 2 GEMM (bf16 split MMA) ----
    k_gemm_mma<<<mb, 256, GEMM_SMEM>>>(W2, N);
    // ---- layer-2 gather + relu + dot (warp per node) ----
    k_gather_dot<<<wb, 256>>>(b2, N);
    // ---- layer-3 scalar aggregate + pool ----
    k_spool<<<(N + 255) / 256, 256>>>(batch, out, N);
}

// round 17
// speedup vs baseline: 1.1759x; 1.0119x over previous
#include <cuda_runtime.h>
#include <cuda_bf16.h>
#include <cstdint>

#define MAXN 100000
#define MAXE 1600000
#define HDIM 128
#define FIN  9
#define GMAX 256
#define SCAN_B 256
#define MAXBLK 512
#define KC   64                 // k per staging phase (bf16 pairs: 32 uints)
#define PC   (KC / 2)           // k-pairs per phase
#define AST  36                 // pair-stride ≡ 4 (mod 32) -> conflict-free frags
#define GEMM_SMEM (4 * 128 * AST * 4)   // 73728 B -> 2 CTA/SM

// -------- scratch (device symbols only; NEVER pass from host — GB300 ATS trap) ----
__device__ __align__(128) float g_dinv[MAXN];
__device__ __align__(128) __nv_bfloat16 g_bufA16[MAXN * HDIM];  // pre-agg, PRE-SCALED by dinv[row]
__device__ __align__(128) float g_bufB[MAXN * HDIM];            // layer-1 output (fp32)
__device__ __align__(128) float g_xs[MAXN * FIN];               // x PRE-SCALED by dinv
__device__ __align__(128) float g_s[MAXN];       // dinv[w]·(relu(h2)·w~)  (pre-scaled)
__device__ __align__(128) float g_wtld[HDIM];    // w~ = W3 @ lin_w
__device__ int   g_degc[MAXN];
__device__ int   g_rowstart[MAXN + 1];
__device__ int   g_cursor[MAXN];
__device__ int   g_bsum[MAXBLK];
__device__ __align__(128) int g_csrc[MAXE];      // CSR src only (weights factorized away)
__device__ int   g_lo[GMAX];
__device__ int   g_hi[GMAX];

// fp32 -> bf16 hi + bf16 lo (Dekker residual)
__device__ __forceinline__ void bf16split(float f, __nv_bfloat16& hi, __nv_bfloat16& lo) {
    hi = __float2bfloat16(f);
    lo = __float2bfloat16(f - __bfloat162float(hi));
}
__device__ __forceinline__ unsigned packbf(__nv_bfloat16 a, __nv_bfloat16 b) {
    __nv_bfloat162 p = __halves2bfloat162(a, b);
    return *reinterpret_cast<unsigned*>(&p);
}

// ====== setup: clear + (last block) w~ gemv + out head init ======
__global__ void k_clear(int n, int g, int nb,
                        const float* __restrict__ W3, const float* __restrict__ b3,
                        const float* __restrict__ lin_w, const float* __restrict__ lb,
                        float* __restrict__ out) {
    if ((int)blockIdx.x == nb) {
        int k = threadIdx.x;
        __shared__ float sb[HDIM];
        if (k < HDIM) {
            float s = 0.f;
#pragma unroll 8
            for (int c = 0; c < HDIM; c++) s += W3[k * HDIM + c] * lin_w[c];
            g_wtld[k] = s;
            sb[k] = b3[k] * lin_w[k];
        }
        __syncthreads();
        for (int off = HDIM / 2; off > 0; off >>= 1) {
            if (k < off) sb[k] += sb[k + off];
            __syncthreads();
        }
        if (k < g) out[k] = sb[0] + lb[0];
        return;
    }
    int i = blockIdx.x * blockDim.x + threadIdx.x;
    if (i < n) g_degc[i] = 0;
    if (i < g) { g_lo[i] = 0; g_hi[i] = 0; }
}

__global__ void k_deg(const int* __restrict__ dst, int E) {
    int e = blockIdx.x * blockDim.x + threadIdx.x;
    if (e < E) atomicAdd(&g_degc[dst[e]], 1);
}

__global__ void k_scan1(int n) {
    __shared__ int sh[SCAN_B];
    int i = blockIdx.x * SCAN_B + threadIdx.x;
    int v = (i < n) ? g_degc[i] : 0;
    if (i < n) g_dinv[i] = rsqrtf((float)(v + 1));
    sh[threadIdx.x] = v;
    __syncthreads();
    for (int off = 1; off < SCAN_B; off <<= 1) {
        int t = (threadIdx.x >= (unsigned)off) ? sh[threadIdx.x - off] : 0;
        __syncthreads();
        sh[threadIdx.x] += t;
        __syncthreads();
    }
    if (i < n) g_rowstart[i] = sh[threadIdx.x] - v;
    if (threadIdx.x == SCAN_B - 1) g_bsum[blockIdx.x] = sh[SCAN_B - 1];
}

// finalize rowstart + cursors + bounds + PRE-SCALED x (xs = x * dinv)
__global__ void k_scan3(const int* __restrict__ batch, const float* __restrict__ x,
                        int n, int E) {
    __shared__ int red[SCAN_B];
    int b = blockIdx.x;
    int partial = 0;
    for (int j = threadIdx.x; j < b; j += SCAN_B) partial += g_bsum[j];
    red[threadIdx.x] = partial;
    __syncthreads();
    for (int off = SCAN_B / 2; off > 0; off >>= 1) {
        if (threadIdx.x < (unsigned)off) red[threadIdx.x] += red[threadIdx.x + off];
        __syncthreads();
    }
    int boff = red[0];

    int i = b * SCAN_B + threadIdx.x;
    if (i < n) {
        int r = g_rowstart[i] + boff;
        g_rowstart[i] = r;
        g_cursor[i] = r;
        int bb = batch[i];
        if (i == 0) g_lo[bb] = 0;
        else {
            int pb = batch[i - 1];
            if (pb != bb) { g_lo[bb] = i; g_hi[pb] = i; }
        }
        if (i == n - 1) g_hi[bb] = n;
        float di = g_dinv[i];
#pragma unroll
        for (int f = 0; f < FIN; f++)
            g_xs[i * FIN + f] = x[i * FIN + f] * di;
    } else if (i == n) {
        g_rowstart[n] = E;
    }
}

// fill CSR: src only, 4B store
__global__ void k_fill(const int* __restrict__ src, const int* __restrict__ dst, int E) {
    int e = blockIdx.x * blockDim.x + threadIdx.x;
    if (e >= E) return;
    int d = dst[e];
    int pos = atomicAdd(&g_cursor[d], 1);
    g_csrc[pos] = src[e];
}

// ======= layer 1: bufB = (Â X) W1 + b1  via unweighted sum of xs + dinv scale ====
__global__ void __launch_bounds__(256) k_layer1(const float* __restrict__ W,
                                                const float* __restrict__ bias, int n) {
    __shared__ float sW1[FIN * HDIM];   // 4.6 KB
    __shared__ float sB[HDIM];
    for (int i = threadIdx.x; i < FIN * HDIM; i += 256) sW1[i] = W[i];
    if (threadIdx.x < HDIM) sB[threadIdx.x] = bias[threadIdx.x];
    __syncthreads();

    int w = (blockIdx.x * blockDim.x + threadIdx.x) >> 5;
    if (w >= n) return;
    int lane = threadIdx.x & 31;
    int rs = g_rowstart[w], re = g_rowstart[w + 1];
    float di = g_dinv[w];
    bool act = lane < FIN;
    float acc = 0.f;
    if (act) acc = g_xs[w * FIN + lane];          // self (pre-scaled)
    int j = rs;
    for (; j + 7 < re; j += 8) {
        int s0 = g_csrc[j],     s1 = g_csrc[j + 1];
        int s2 = g_csrc[j + 2], s3 = g_csrc[j + 3];
        int s4 = g_csrc[j + 4], s5 = g_csrc[j + 5];
        int s6 = g_csrc[j + 6], s7 = g_csrc[j + 7];
        if (act) {
            acc += g_xs[s0 * FIN + lane] + g_xs[s1 * FIN + lane]
                 + g_xs[s2 * FIN + lane] + g_xs[s3 * FIN + lane]
                 + g_xs[s4 * FIN + lane] + g_xs[s5 * FIN + lane]
                 + g_xs[s6 * FIN + lane] + g_xs[s7 * FIN + lane];
        }
    }
    for (; j < re; j++) {
        int s = g_csrc[j];
        if (act) acc += g_xs[s * FIN + lane];
    }
    acc *= di;                                    // single dst scale
    // broadcast 9 aggregated features, GEMV
    float xv[FIN];
#pragma unroll
    for (int f = 0; f < FIN; f++) xv[f] = __shfl_sync(0xffffffffu, acc, f);
    int c = lane * 4;
    float4 o = make_float4(sB[c], sB[c + 1], sB[c + 2], sB[c + 3]);
#pragma unroll
    for (int f = 0; f < FIN; f++) {
        float4 wv = *reinterpret_cast<const float4*>(&sW1[f * HDIM + c]);
        o.x += xv[f] * wv.x; o.y += xv[f] * wv.y;
        o.z += xv[f] * wv.z; o.w += xv[f] * wv.w;
    }
    *reinterpret_cast<float4*>(&g_bufB[w * HDIM + c]) = o;
}

// ====== hidden GEMM: 3-term bf16 split warp-MMA; epilogue pre-scales by dinv ======
__global__ void __launch_bounds__(256) k_gemm_mma(const float* __restrict__ W, int n) {
    extern __shared__ unsigned smu[];
    unsigned* sAhi = smu;
    unsigned* sAlo = smu + 128 * AST;
    unsigned* sWhi = smu + 2 * 128 * AST;
    unsigned* sWlo = smu + 3 * 128 * AST;
    int tid = threadIdx.x;
    int node0 = blockIdx.x * 128;

    int wid = tid >> 5, lane = tid & 31;
    int m0 = wid * 16;
    int lr = lane >> 2;
    int lc = lane & 3;

    float d[16][4];
#pragma unroll
    for (int t = 0; t < 16; t++)
#pragma unroll
        for (int j = 0; j < 4; j++) d[t][j] = 0.f;

#pragma unroll 1
    for (int p = 0; p < 2; p++) {
        int k0 = p * KC;
        if (p) __syncthreads();
        for (int idx = tid; idx < 128 * PC; idx += 256) {
            int r = idx >> 5, pc = idx & (PC - 1);
            int k = k0 + pc * 2;
            float v0 = 0.f, v1 = 0.f;
            if (node0 + r < n) {
                const float* row = &g_bufB[(node0 + r) * HDIM + k];
                v0 = fmaxf(row[0], 0.f);
                v1 = fmaxf(row[1], 0.f);
            }
            __nv_bfloat16 h0, l0, h1, l1;
            bf16split(v0, h0, l0);
            bf16split(v1, h1, l1);
            sAhi[r * AST + pc] = packbf(h0, h1);
            sAlo[r * AST + pc] = packbf(l0, l1);
        }
        for (int idx = tid; idx < PC * 128; idx += 256) {
            int pc = idx >> 7, nn = idx & 127;
            int k = k0 + pc * 2;
            float v0 = __ldg(&W[k * HDIM + nn]);
            float v1 = __ldg(&W[(k + 1) * HDIM + nn]);
            __nv_bfloat16 h0, l0, h1, l1;
            bf16split(v0, h0, l0);
            bf16split(v1, h1, l1);
            sWhi[nn * AST + pc] = packbf(h0, h1);
            sWlo[nn * AST + pc] = packbf(l0, l1);
        }
        __syncthreads();

        const unsigned* pah = &sAhi[(m0 + lr) * AST + lc];
        const unsigned* pal = &sAlo[(m0 + lr) * AST + lc];

#pragma unroll
        for (int kc = 0; kc < PC / 8; kc++) {
            int kb = kc * 8;
            unsigned ah0 = pah[kb],     ah1 = pah[8 * AST + kb];
            unsigned ah2 = pah[kb + 4], ah3 = pah[8 * AST + kb + 4];
            unsigned al0 = pal[kb],     al1 = pal[8 * AST + kb];
            unsigned al2 = pal[kb + 4], al3 = pal[8 * AST + kb + 4];
#pragma unroll
            for (int t = 0; t < 16; t++) {
                const unsigned* pbh = &sWhi[(t * 8 + lr) * AST + kb + lc];
                const unsigned* pbl = &sWlo[(t * 8 + lr) * AST + kb + lc];
                unsigned bh0 = pbh[0], bh1 = pbh[4];
                unsigned bl0 = pbl[0], bl1 = pbl[4];
                asm volatile(
                    "mma.sync.aligned.m16n8k16.row.col.f32.bf16.bf16.f32 "
                    "{%0,%1,%2,%3}, {%4,%5,%6,%7}, {%8,%9}, {%0,%1,%2,%3};"
                    : "+f"(d[t][0]), "+f"(d[t][1]), "+f"(d[t][2]), "+f"(d[t][3])
                    : "r"(ah0), "r"(ah1), "r"(ah2), "r"(ah3), "r"(bh0), "r"(bh1));
                asm volatile(
                    "mma.sync.aligned.m16n8k16.row.col.f32.bf16.bf16.f32 "
                    "{%0,%1,%2,%3}, {%4,%5,%6,%7}, {%8,%9}, {%0,%1,%2,%3};"
                    : "+f"(d[t][0]), "+f"(d[t][1]), "+f"(d[t][2]), "+f"(d[t][3])
                    : "r"(ah0), "r"(ah1), "r"(ah2), "r"(ah3), "r"(bl0), "r"(bl1));
                asm volatile(
                    "mma.sync.aligned.m16n8k16.row.col.f32.bf16.bf16.f32 "
                    "{%0,%1,%2,%3}, {%4,%5,%6,%7}, {%8,%9}, {%0,%1,%2,%3};"
                    : "+f"(d[t][0]), "+f"(d[t][1]), "+f"(d[t][2]), "+f"(d[t][3])
                    : "r"(al0), "r"(al1), "r"(al2), "r"(al3), "r"(bh0), "r"(bh1));
            }
        }
    }

    int row0 = node0 + m0 + lr;
    int row1 = row0 + 8;
    float dv0 = (row0 < n) ? g_dinv[row0] : 0.f;
    float dv1 = (row1 < n) ? g_dinv[row1] : 0.f;
#pragma unroll
    for (int t = 0; t < 16; t++) {
        int col = t * 8 + lc * 2;
        if (row0 < n) {
            __nv_bfloat162 pp = __floats2bfloat162_rn(d[t][0] * dv0, d[t][1] * dv0);
            *reinterpret_cast<unsigned*>(&g_bufA16[row0 * HDIM + col]) =
                *reinterpret_cast<unsigned*>(&pp);
        }
        if (row1 < n) {
            __nv_bfloat162 pp = __floats2bfloat162_rn(d[t][2] * dv1, d[t][3] * dv1);
            *reinterpret_cast<unsigned*>(&g_bufA16[row1 * HDIM + col]) =
                *reinterpret_cast<unsigned*>(&pp);
        }
    }
}

// ======= layer-2 aggregate (unweighted) + dinv + bias + relu + dot(w~) =======
__device__ __forceinline__ float4 ld_row4(int node, int q) {
    uint2 raw = *reinterpret_cast<const uint2*>(&g_bufA16[node * HDIM + q]);
    __nv_bfloat162 p0 = *reinterpret_cast<__nv_bfloat162*>(&raw.x);
    __nv_bfloat162 p1 = *reinterpret_cast<__nv_bfloat162*>(&raw.y);
    float2 f0 = __bfloat1622float2(p0);
    float2 f1 = __bfloat1622float2(p1);
    return make_float4(f0.x, f0.y, f1.x, f1.y);
}

__global__ void k_gather_dot(const float* __restrict__ bias, int n) {
    int w = (blockIdx.x * blockDim.x + threadIdx.x) >> 5;
    if (w >= n) return;
    int lane = threadIdx.x & 31;
    int q = lane * 4;
    int rs = g_rowstart[w], re = g_rowstart[w + 1];
    float di = g_dinv[w];
    float4 acc = ld_row4(w, q);                  // self (rows pre-scaled)

    int j = rs;
    for (; j + 7 < re; j += 8) {
        int s0 = g_csrc[j],     s1 = g_csrc[j + 1];
        int s2 = g_csrc[j + 2], s3 = g_csrc[j + 3];
        int s4 = g_csrc[j + 4], s5 = g_csrc[j + 5];
        int s6 = g_csrc[j + 6], s7 = g_csrc[j + 7];
        float4 v0 = ld_row4(s0, q), v1 = ld_row4(s1, q);
        float4 v2 = ld_row4(s2, q), v3 = ld_row4(s3, q);
        float4 v4 = ld_row4(s4, q), v5 = ld_row4(s5, q);
        float4 v6 = ld_row4(s6, q), v7 = ld_row4(s7, q);
        acc.x += v0.x + v1.x + v2.x + v3.x + v4.x + v5.x + v6.x + v7.x;
        acc.y += v0.y + v1.y + v2.y + v3.y + v4.y + v5.y + v6.y + v7.y;
        acc.z += v0.z + v1.z + v2.z + v3.z + v4.z + v5.z + v6.z + v7.z;
        acc.w += v0.w + v1.w + v2.w + v3.w + v4.w + v5.w + v6.w + v7.w;
    }
    for (; j < re; j++) {
        float4 v = ld_row4(g_csrc[j], q);
        acc.x += v.x; acc.y += v.y; acc.z += v.z; acc.w += v.w;
    }
    float4 b = __ldg(reinterpret_cast<const float4*>(&bias[q]));
    acc.x = acc.x * di + b.x; acc.y = acc.y * di + b.y;
    acc.z = acc.z * di + b.z; acc.w = acc.w * di + b.w;
    float4 wt = __ldg(reinterpret_cast<const float4*>(&g_wtld[q]));
    float v = fmaxf(acc.x, 0.f) * wt.x + fmaxf(acc.y, 0.f) * wt.y
            + fmaxf(acc.z, 0.f) * wt.z + fmaxf(acc.w, 0.f) * wt.w;
#pragma unroll
    for (int off = 16; off > 0; off >>= 1)
        v += __shfl_down_sync(0xffffffffu, v, off);
    if (lane == 0) g_s[w] = di * v;              // pre-scale for spool
}

// scalar aggregate + pool: out[batch[d]] += dinv[d]·(g_s[d] + Σ g_s[src]) / cnt
__global__ void k_spool(const int* __restrict__ batch, float* __restrict__ out, int n) {
    int d = blockIdx.x * blockDim.x + threadIdx.x;
    if (d >= n) return;
    int rs = g_rowstart[d], re = g_rowstart[d + 1];
    float acc = g_s[d];                          // self (pre-scaled)
    int j = rs;
    for (; j + 7 < re; j += 8) {
        int s0 = g_csrc[j],     s1 = g_csrc[j + 1];
        int s2 = g_csrc[j + 2], s3 = g_csrc[j + 3];
        int s4 = g_csrc[j + 4], s5 = g_csrc[j + 5];
        int s6 = g_csrc[j + 6], s7 = g_csrc[j + 7];
        acc += g_s[s0] + g_s[s1] + g_s[s2] + g_s[s3]
             + g_s[s4] + g_s[s5] + g_s[s6] + g_s[s7];
    }
    for (; j < re; j++) acc += g_s[g_csrc[j]];
    int b = batch[d];
    float inv = g_dinv[d] / (float)(g_hi[b] - g_lo[b]);
    asm volatile("red.global.add.f32 [%0], %1;" :: "l"(&out[b]), "f"(acc * inv) : "memory");
}

extern "C" void kernel_launch(void* const* d_in, const int* in_sizes, int n_in,
                              void* d_out, int out_size) {
    const float* x     = (const float*)d_in[0];
    const int*   ei    = (const int*)d_in[1];
    const int*   batch = (const int*)d_in[2];
    const float* W1 = (const float*)d_in[3];
    const float* b1 = (const float*)d_in[4];
    const float* W2 = (const float*)d_in[5];
    const float* b2 = (const float*)d_in[6];
    const float* W3 = (const float*)d_in[7];
    const float* b3 = (const float*)d_in[8];
    const float* lw = (const float*)d_in[9];
    const float* lb = (const float*)d_in[10];
    float* out = (float*)d_out;

    int N = in_sizes[0] / FIN;
    int E = in_sizes[1] / 2;
    int G = out_size;

    const int* src = ei;
    const int* dst = ei + E;

    int nb  = (N + SCAN_B - 1) / SCAN_B;
    int eb  = (E + 255) / 256;
    int wb  = (N * 32 + 255) / 256;
    int mb  = (N + 127) / 128;

    cudaFuncSetAttribute(k_gemm_mma, cudaFuncAttributeMaxDynamicSharedMemorySize, GEMM_SMEM);

    // ---- CSR build + bounds (+ fused gemv/out-head in clear) ----
    k_clear<<<nb + 1, SCAN_B>>>(N, G, nb, W3, b3, lw, lb, out);
    k_deg<<<eb, 256>>>(dst, E);
    k_scan1<<<nb, SCAN_B>>>(N);
    k_scan3<<<(N + 256) / 256, 256>>>(batch, x, N, E);
    k_fill<<<eb, 256>>>(src, dst, E);

    // ---- layer 1 (unweighted gather of pre-scaled xs + GEMV) ----
    k_layer1<<<wb, 256>>>(W1, b1, N);
    // ---- layer 2 GEMM (bf16 split MMA; epilogue pre-scales rows) ----
    k_gemm_mma<<<mb, 256, GEMM_SMEM>>>(W2, N);
    // ---- layer-2 gather + relu + dot ----
    k_gather_dot<<<wb, 256>>>(b2, N);
    // ---- layer-3 scalar aggregate + pool ----
    k_spool<<<(N + 255) / 256, 256>>>(batch, out, N);
}